// round 11
// baseline (speedup 1.0000x reference)
#include <cuda_runtime.h>
#include <math.h>

#define MAX_TRI 512
#define WSTRIDE 33      // odd stride -> conflict-free scalar weight reads
#define THREADS 256
#define FSLOTS  3       // fixed slots cover j < jbase (lin+cubic = 735 <= 768)

__device__ float g_cw[MAX_TRI * WSTRIDE];
__device__ int   g_lo[MAX_TRI];     // even-aligned band start
__device__ int   g_len[MAX_TRI];    // band length from g_lo (<= 32)

// ---------------------------------------------------------------------------
// cp.async helpers
// ---------------------------------------------------------------------------
__device__ __forceinline__ void cp_async16(float4* sptr, const float4* gptr)
{
    unsigned s = (unsigned)__cvta_generic_to_shared(sptr);
    asm volatile("cp.async.cg.shared.global [%0], [%1], 16;\n" :: "r"(s), "l"(gptr));
}
#define CP_COMMIT()  asm volatile("cp.async.commit_group;\n" ::)
#define CP_WAIT1()   asm volatile("cp.async.wait_group 1;\n" ::)
#define CP_WAIT0()   asm volatile("cp.async.wait_group 0;\n" ::)

// ---------------------------------------------------------------------------
// Preprocess: compact the finite band of each triangular-weight row,
// band start aligned DOWN to an even input bin.
// ---------------------------------------------------------------------------
__global__ void prep_kernel(const float* __restrict__ w, int n_tri, int n_in)
{
    int j = blockIdx.x;
    if (j >= n_tri) return;
    __shared__ int s_lo, s_hi;
    if (threadIdx.x == 0) { s_lo = n_in; s_hi = 0; }
    __syncthreads();

    const float* row = w + (size_t)j * n_in;
    int lo = n_in, hi = 0;
    for (int c = threadIdx.x; c < n_in; c += blockDim.x) {
        float v = row[c];
        if (v > -1e30f) { lo = min(lo, c); hi = max(hi, c); }
    }
    atomicMin(&s_lo, lo);
    atomicMax(&s_hi, hi);
    __syncthreads();

    const int lof = s_lo, hif = s_hi;
    int L = lof & ~1;                   // even-aligned start
    int len = hif - L + 1;
    if (len > 32) len = 32;             // safety clamp (actual max ~30)
    if (threadIdx.x == 0) { g_lo[j] = L; g_len[j] = len; }
    for (int k = threadIdx.x; k < WSTRIDE; k += blockDim.x) {
        int bin = L + k;
        g_cw[j * WSTRIDE + k] =
            (bin >= lof && bin <= hif && k < len) ? row[bin] : -INFINITY;
    }
}

__device__ __forceinline__ float cubic_eval(const float* xs, int i0, float f)
{
    float xm = xs[i0 - 1], c0 = xs[i0], c1 = xs[i0 + 1], c2 = xs[i0 + 2];
    return c0 + 0.5f * f * (c1 - xm +
           f * (2.f * xm - 5.f * c0 + 4.f * c1 - c2 +
           f * (3.f * (c0 - c1) + c2 - xm)));
}

// ---------------------------------------------------------------------------
// Main kernel: persistent blocks; 4 same-shift rows per pass; double-buffered
// 16B cp.async staging; float2 tri reads; RANK-BALANCED tri->warp assignment.
// ---------------------------------------------------------------------------
__global__ void __launch_bounds__(THREADS, 2)
logscale_kernel(const float* __restrict__ x,
                const float* __restrict__ flin,
                const float* __restrict__ fcub,
                const int*   __restrict__ pidx,
                float*       __restrict__ out,
                int n_rows, int n_in, int n_lin, int n_cub, int n_tri,
                int xpitch, int n_items)
{
    extern __shared__ float smem[];
    const int n_out = n_lin + n_cub + n_tri;
    const int jbase = n_lin + n_cub;
    const int wtot  = n_tri * WSTRIDE;
    const int bufoff = (wtot + n_tri + 3) & ~3;
    float* sw    = smem;
    int*   s_map = (int*)(smem + wtot);     // n_tri ints: lens, then rank->band
    float* bufs  = smem + bufoff;           // 2 buffers x 4 rows x xpitch

    const int tid = threadIdx.x;
    const int N16 = (n_in + 6) >> 2;        // float4 count per staged row

    // ---- one-time block init -------------------------------------------
    for (int i = tid; i < wtot; i += THREADS) sw[i] = g_cw[i];
    for (int q = tid; q < n_tri; q += THREADS)
        s_map[q] = (g_len[q] + 3) & ~3;     // padded len as sort key
    for (int b = 0; b < 8; b++)             // zero never-staged tails
        for (int i = 4 * N16 + tid; i < xpitch; i += THREADS)
            bufs[b * xpitch + i] = 0.f;
    __syncthreads();

    // Descending-length ranks for bands q=tid and q=tid+THREADS.
    int rk1 = 0, rk2 = 0;
    const int qa = tid, qb = tid + THREADS;
    const int la = (qa < n_tri) ? s_map[qa] : -1;
    const int lb = (qb < n_tri) ? s_map[qb] : -1;
    for (int q = 0; q < n_tri; q++) {
        const int lq = s_map[q];
        rk1 += (lq > la) || (lq == la && q < qa);
        rk2 += (lq > lb) || (lq == lb && q < qb);
    }
    __syncthreads();
    if (qa < n_tri) s_map[rk1] = qa;
    if (qb < n_tri) s_map[rk2] = qb;
    __syncthreads();

    // Thread t takes rank r1 = 8*lane + warp  (spreads long bands over warps),
    // plus leftover rank 256+r1 (short bands) if it exists.
    const int r1 = ((tid & 31) << 3) + (tid >> 5);
    int q1 = -1, lo1 = 0, lp1 = 0, wo1 = 0, j1 = 0;
    int q2 = -1, lo2_, lp2 = 0, wo2 = 0, j2 = 0;
    lo2_ = 0;
    if (r1 < n_tri && r1 < THREADS) {
        q1 = s_map[r1];
        lo1 = g_lo[q1]; lp1 = (g_len[q1] + 3) & ~3;
        wo1 = q1 * WSTRIDE; j1 = jbase + q1;
    }
    if (THREADS + r1 < n_tri) {
        q2 = s_map[THREADS + r1];
        lo2_ = g_lo[q2]; lp2 = (g_len[q2] + 3) & ~3;
        wo2 = q2 * WSTRIDE; j2 = jbase + q2;
    }

    // Fixed slots: lin / cubic only (j < jbase).
    int   kind[FSLOTS], ia[FSLOTS], ib[FSLOTS];
    float ff[FSLOTS];
    #pragma unroll
    for (int s = 0; s < FSLOTS; s++) {
        const int j = tid + s * THREADS;
        kind[s] = 3; ia[s] = 0; ib[s] = 0; ff[s] = 0.f;
        if (j < n_lin) {
            kind[s] = 0;
            ia[s] = pidx[j];
            ib[s] = pidx[j + n_lin];
            ff[s] = flin[j];
        } else if (j < jbase) {
            kind[s] = 1;
            float fc = fcub[j - n_lin];
            int i0 = (int)floorf(fc);
            ia[s] = i0;
            ff[s] = fc - (float)i0;
        }
    }
    __syncthreads();

    // ---- pipeline ------------------------------------------------------
    const int stride = gridDim.x;

    auto stage = [&](int m, float* dst) {
        const int g = m >> 2, c = m & 3;
        const int rbase = 16 * g + c;
        #pragma unroll
        for (int i = 0; i < 4; i++) {
            int r = rbase + 4 * i;
            if (r >= n_rows) r = (rbase < n_rows) ? rbase : c;
            const float4* src = (const float4*)(x + (size_t)r * n_in - c);
            float4* d4 = (float4*)(dst + i * xpitch);
            for (int t = tid; t < N16; t += THREADS) cp_async16(&d4[t], &src[t]);
        }
    };

    int m = blockIdx.x;
    if (m < n_items) stage(m, bufs);
    CP_COMMIT();

    int it = 0;
    for (; m < n_items; m += stride, it++) {
        float* cur  = bufs + (it & 1) * (4 * xpitch);
        float* nbuf = bufs + ((it + 1) & 1) * (4 * xpitch);

        const int nxt = m + stride;
        if (nxt < n_items) { stage(nxt, nbuf); CP_COMMIT(); CP_WAIT1(); }
        else               { CP_WAIT0(); }
        __syncthreads();

        const int g = m >> 2, c = m & 3;
        const int rbase = 16 * g + c;
        const float* xr0 = cur + c;
        const float* xr1 = cur + xpitch + c;
        const float* xr2 = cur + 2 * xpitch + c;
        const float* xr3 = cur + 3 * xpitch + c;
        const bool w0 = (rbase      < n_rows);
        const bool w1 = (rbase + 4  < n_rows);
        const bool w2 = (rbase + 8  < n_rows);
        const bool w3 = (rbase + 12 < n_rows);
        float* o0 = out + (size_t)rbase * n_out;
        float* o1 = o0 + (size_t)4  * n_out;
        float* o2 = o0 + (size_t)8  * n_out;
        float* o3 = o0 + (size_t)12 * n_out;
        const int pi = c & 1;

        #pragma unroll
        for (int s = 0; s < FSLOTS; s++) {
            if (kind[s] == 3) continue;
            const int j = tid + s * THREADS;
            float v0, v1, v2, v3;
            if (kind[s] == 0) {
                const int a = ia[s], b = ib[s];
                const float f = ff[s];
                float a0 = xr0[a], b0 = xr0[b]; v0 = a0 + f * (b0 - a0);
                float a1 = xr1[a], b1 = xr1[b]; v1 = a1 + f * (b1 - a1);
                float a2 = xr2[a], b2 = xr2[b]; v2 = a2 + f * (b2 - a2);
                float a3 = xr3[a], b3 = xr3[b]; v3 = a3 + f * (b3 - a3);
            } else {
                const int i0 = ia[s];
                const float f = ff[s];
                v0 = cubic_eval(xr0, i0, f);
                v1 = cubic_eval(xr1, i0, f);
                v2 = cubic_eval(xr2, i0, f);
                v3 = cubic_eval(xr3, i0, f);
            }
            if (w0) o0[j] = v0;
            if (w1) o1[j] = v1;
            if (w2) o2[j] = v2;
            if (w3) o3[j] = v3;
        }

        // Banded max-plus (rank-balanced; up to two bands per thread).
        auto tri4 = [&](int lo, int lenp, int wo, int j) {
            float m0 = -INFINITY, m1 = -INFINITY, m2 = -INFINITY, m3 = -INFINITY;
            if (pi) {
                const float wv = sw[wo];
                m0 = xr0[lo] + wv; m1 = xr1[lo] + wv;
                m2 = xr2[lo] + wv; m3 = xr3[lo] + wv;
            }
            const float2* p0 = (const float2*)(xr0 + lo + pi);
            const float2* p1 = (const float2*)(xr1 + lo + pi);
            const float2* p2 = (const float2*)(xr2 + lo + pi);
            const float2* p3 = (const float2*)(xr3 + lo + pi);
            const float*  wp = sw + wo + pi;
            const int half = lenp >> 1;
            #pragma unroll 2
            for (int t = 0; t < half; t++) {
                const float wa = wp[2 * t], wb = wp[2 * t + 1];
                float2 v;
                v = p0[t]; m0 = fmaxf(m0, v.x + wa); m0 = fmaxf(m0, v.y + wb);
                v = p1[t]; m1 = fmaxf(m1, v.x + wa); m1 = fmaxf(m1, v.y + wb);
                v = p2[t]; m2 = fmaxf(m2, v.x + wa); m2 = fmaxf(m2, v.y + wb);
                v = p3[t]; m3 = fmaxf(m3, v.x + wa); m3 = fmaxf(m3, v.y + wb);
            }
            if (w0) o0[j] = m0;
            if (w1) o1[j] = m1;
            if (w2) o2[j] = m2;
            if (w3) o3[j] = m3;
        };
        if (q1 >= 0) tri4(lo1, lp1, wo1, j1);
        if (q2 >= 0) tri4(lo2_, lp2, wo2, j2);

        __syncthreads();
    }
}

// ---------------------------------------------------------------------------
extern "C" void kernel_launch(void* const* d_in, const int* in_sizes, int n_in_arr,
                              void* d_out, int out_size)
{
    const float* x    = (const float*)d_in[0];
    const float* flin = (const float*)d_in[1];
    const float* fcub = (const float*)d_in[2];
    const float* w    = (const float*)d_in[3];
    const int*   pidx = (const int*)d_in[4];

    const int n_lin = in_sizes[1];
    const int n_cub = in_sizes[2];

    // Solve (n_tri, n_in, n_rows) from the size system; unique factorization.
    int n_tri = 0, N_IN = 0, n_rows = 0;
    for (int t = 1; t <= MAX_TRI; t++) {
        if (in_sizes[3] % t) continue;
        long ni = in_sizes[3] / t;
        if (ni <= 0 || (long)in_sizes[0] % ni) continue;
        long rows = (long)in_sizes[0] / ni;
        if (rows * (long)(n_lin + n_cub + t) == (long)out_size) {
            n_tri = t; N_IN = (int)ni; n_rows = (int)rows;
            break;
        }
    }
    if (n_tri == 0) return;

    prep_kernel<<<n_tri, 256>>>(w, n_tri, N_IN);

    const int N16    = (N_IN + 6) >> 2;
    const int xpitch = 4 * N16 + 8;                       // staged + pad, mult of 4
    const int bufoff = (n_tri * WSTRIDE + n_tri + 3) & ~3;
    const int smem_bytes = (bufoff + 8 * xpitch) * (int)sizeof(float);
    cudaFuncSetAttribute(logscale_kernel,
                         cudaFuncAttributeMaxDynamicSharedMemorySize, smem_bytes);

    const int n_items = 4 * ((n_rows + 15) / 16);         // 4 rows per item
    int grid = 148 * 2;                                   // persistent: 2 blocks / SM
    if (grid > n_items) grid = n_items;

    logscale_kernel<<<grid, THREADS, smem_bytes>>>(
        x, flin, fcub, pidx, (float*)d_out,
        n_rows, N_IN, n_lin, n_cub, n_tri, xpitch, n_items);
}

// round 13
// speedup vs baseline: 1.2797x; 1.2797x over previous
#include <cuda_runtime.h>
#include <math.h>

#define MAX_TRI 512
#define WSTRIDE 33      // odd stride -> conflict-free scalar weight reads
#define THREADS 256
#define FSLOTS  3       // fixed slots cover j < jbase (lin+cubic = 735 <= 768)

__device__ float g_cw[MAX_TRI * WSTRIDE];
__device__ int   g_lo[MAX_TRI];     // even-aligned band start
__device__ int   g_len[MAX_TRI];    // band length from g_lo (<= 32)

// ---------------------------------------------------------------------------
// cp.async helpers
// ---------------------------------------------------------------------------
__device__ __forceinline__ void cp_async16(float4* sptr, const float4* gptr)
{
    unsigned s = (unsigned)__cvta_generic_to_shared(sptr);
    asm volatile("cp.async.cg.shared.global [%0], [%1], 16;\n" :: "r"(s), "l"(gptr));
}
#define CP_COMMIT()  asm volatile("cp.async.commit_group;\n" ::)
#define CP_WAIT1()   asm volatile("cp.async.wait_group 1;\n" ::)
#define CP_WAIT0()   asm volatile("cp.async.wait_group 0;\n" ::)

// ---------------------------------------------------------------------------
// Preprocess: compact the finite band of each triangular-weight row,
// band start aligned DOWN to an even input bin. float4 scan when aligned.
// ---------------------------------------------------------------------------
__global__ void prep_kernel(const float* __restrict__ w, int n_tri, int n_in)
{
    int j = blockIdx.x;
    if (j >= n_tri) return;
    __shared__ int s_lo, s_hi;
    if (threadIdx.x == 0) { s_lo = n_in; s_hi = 0; }
    __syncthreads();

    const float* row = w + (size_t)j * n_in;
    int lo = n_in, hi = 0;
    const int n4 = n_in >> 2;
    if ((((size_t)row) & 15) == 0) {
        const float4* row4 = (const float4*)row;
        for (int c4 = threadIdx.x; c4 < n4; c4 += blockDim.x) {
            float4 v = row4[c4];
            int c = c4 << 2;
            if (v.x > -1e30f) { lo = min(lo, c);     hi = max(hi, c);     }
            if (v.y > -1e30f) { lo = min(lo, c + 1); hi = max(hi, c + 1); }
            if (v.z > -1e30f) { lo = min(lo, c + 2); hi = max(hi, c + 2); }
            if (v.w > -1e30f) { lo = min(lo, c + 3); hi = max(hi, c + 3); }
        }
        for (int c = (n4 << 2) + threadIdx.x; c < n_in; c += blockDim.x) {
            float v = row[c];
            if (v > -1e30f) { lo = min(lo, c); hi = max(hi, c); }
        }
    } else {
        for (int c = threadIdx.x; c < n_in; c += blockDim.x) {
            float v = row[c];
            if (v > -1e30f) { lo = min(lo, c); hi = max(hi, c); }
        }
    }
    atomicMin(&s_lo, lo);
    atomicMax(&s_hi, hi);
    __syncthreads();

    const int lof = s_lo, hif = s_hi;
    int L = lof & ~1;                   // even-aligned start
    int len = hif - L + 1;
    if (len > 32) len = 32;             // safety clamp (actual max ~30)
    if (threadIdx.x == 0) { g_lo[j] = L; g_len[j] = len; }
    for (int k = threadIdx.x; k < WSTRIDE; k += blockDim.x) {
        int bin = L + k;
        g_cw[j * WSTRIDE + k] =
            (bin >= lof && bin <= hif && k < len) ? row[bin] : -INFINITY;
    }
}

__device__ __forceinline__ float cubic_eval(const float* xs, int i0, float f)
{
    float xm = xs[i0 - 1], c0 = xs[i0], c1 = xs[i0 + 1], c2 = xs[i0 + 2];
    return c0 + 0.5f * f * (c1 - xm +
           f * (2.f * xm - 5.f * c0 + 4.f * c1 - c2 +
           f * (3.f * (c0 - c1) + c2 - xm)));
}

// ---------------------------------------------------------------------------
// Main kernel: persistent blocks; 4 same-shift rows per pass; double-buffered
// 16B cp.async staging; float2 tri reads; warp-strided 8-band chunk balance.
// ---------------------------------------------------------------------------
__global__ void __launch_bounds__(THREADS, 2)
logscale_kernel(const float* __restrict__ x,
                const float* __restrict__ flin,
                const float* __restrict__ fcub,
                const int*   __restrict__ pidx,
                float*       __restrict__ out,
                int n_rows, int n_in, int n_lin, int n_cub, int n_tri,
                int xpitch, int n_items)
{
    extern __shared__ float smem[];
    const int n_out = n_lin + n_cub + n_tri;
    const int jbase = n_lin + n_cub;
    const int wtot  = n_tri * WSTRIDE;
    const int bufoff = (wtot + 3) & ~3;
    float* sw   = smem;
    float* bufs = smem + bufoff;            // 2 buffers x 4 rows x xpitch

    const int tid = threadIdx.x;
    const int N16 = (n_in + 6) >> 2;        // float4 count per staged row

    // ---- one-time block init -------------------------------------------
    for (int i = tid; i < wtot; i += THREADS) sw[i] = g_cw[i];
    for (int b = 0; b < 8; b++)             // zero never-staged tails
        for (int i = 4 * N16 + tid; i < xpitch; i += THREADS)
            bufs[b * xpitch + i] = 0.f;

    // Tri band assignment.
    // Shortest bands q = 0 .. n_tri-257 -> slot 2 identity mapping (j = tid+512).
    // Remaining 256 bands -> warp-strided 8-band chunks (balanced):
    //   warp w, lane l: chunk = (l>>3)*8 + w, q3 = (n_tri-256) + chunk*8 + (l&7)
    // Preserves: consecutive q within 8-lane groups (bank-spread weight reads,
    // coalesced 32B store runs) while equalizing per-warp max band length.
    const int qrem = n_tri - 256;           // bands handled by slot 2 (e.g. 33)
    int q3 = -1, lo3 = 0, lp3 = 0, wo3 = 0, j3 = 0;
    if (n_tri >= 256) {
        const int w = tid >> 5, l = tid & 31;
        const int chunk = ((l >> 3) << 3) + w;
        q3 = qrem + (chunk << 3) + (l & 7);
        lo3 = g_lo[q3]; lp3 = (g_len[q3] + 3) & ~3;
        wo3 = q3 * WSTRIDE; j3 = jbase + q3;
    }

    // Fixed slots: slots 0..1 lin/cubic; slot 2 = lin/cubic tail + shortest tri.
    int   kind[FSLOTS], ia[FSLOTS], ib[FSLOTS];
    float ff[FSLOTS];
    #pragma unroll
    for (int s = 0; s < FSLOTS; s++) {
        const int j = tid + s * THREADS;
        kind[s] = 3; ia[s] = 0; ib[s] = 0; ff[s] = 0.f;
        if (j < n_lin) {
            kind[s] = 0;
            ia[s] = pidx[j];
            ib[s] = pidx[j + n_lin];
            ff[s] = flin[j];
        } else if (j < jbase) {
            kind[s] = 1;
            float fc = fcub[j - n_lin];
            int i0 = (int)floorf(fc);
            ia[s] = i0;
            ff[s] = fc - (float)i0;
        } else if (qrem > 0 && j < jbase + qrem) {
            kind[s] = 2;                    // short tri band, identity mapping
            const int q = j - jbase;
            ia[s] = g_lo[q];
            ib[s] = (g_len[q] + 3) & ~3;
        }
    }
    __syncthreads();

    // ---- pipeline ------------------------------------------------------
    const int stride = gridDim.x;

    auto stage = [&](int m, float* dst) {
        const int g = m >> 2, c = m & 3;
        const int rbase = 16 * g + c;
        #pragma unroll
        for (int i = 0; i < 4; i++) {
            int r = rbase + 4 * i;
            if (r >= n_rows) r = (rbase < n_rows) ? rbase : c;
            const float4* src = (const float4*)(x + (size_t)r * n_in - c);
            float4* d4 = (float4*)(dst + i * xpitch);
            for (int t = tid; t < N16; t += THREADS) cp_async16(&d4[t], &src[t]);
        }
    };

    int m = blockIdx.x;
    if (m < n_items) stage(m, bufs);
    CP_COMMIT();

    int it = 0;
    for (; m < n_items; m += stride, it++) {
        float* cur  = bufs + (it & 1) * (4 * xpitch);
        float* nbuf = bufs + ((it + 1) & 1) * (4 * xpitch);

        const int nxt = m + stride;
        if (nxt < n_items) { stage(nxt, nbuf); CP_COMMIT(); CP_WAIT1(); }
        else               { CP_WAIT0(); }
        __syncthreads();

        const int g = m >> 2, c = m & 3;
        const int rbase = 16 * g + c;
        const float* xr0 = cur + c;
        const float* xr1 = cur + xpitch + c;
        const float* xr2 = cur + 2 * xpitch + c;
        const float* xr3 = cur + 3 * xpitch + c;
        const bool w0 = (rbase      < n_rows);
        const bool w1 = (rbase + 4  < n_rows);
        const bool w2 = (rbase + 8  < n_rows);
        const bool w3 = (rbase + 12 < n_rows);
        float* o0 = out + (size_t)rbase * n_out;
        float* o1 = o0 + (size_t)4  * n_out;
        float* o2 = o0 + (size_t)8  * n_out;
        float* o3 = o0 + (size_t)12 * n_out;
        const int pi = c & 1;

        // Banded max-plus for one band, all 4 rows.
        auto tri4 = [&](int lo, int lenp, int wo, int j) {
            float m0 = -INFINITY, m1 = -INFINITY, m2 = -INFINITY, m3 = -INFINITY;
            if (pi) {
                const float wv = sw[wo];
                m0 = xr0[lo] + wv; m1 = xr1[lo] + wv;
                m2 = xr2[lo] + wv; m3 = xr3[lo] + wv;
            }
            const float2* p0 = (const float2*)(xr0 + lo + pi);
            const float2* p1 = (const float2*)(xr1 + lo + pi);
            const float2* p2 = (const float2*)(xr2 + lo + pi);
            const float2* p3 = (const float2*)(xr3 + lo + pi);
            const float*  wp = sw + wo + pi;
            const int half = lenp >> 1;
            #pragma unroll 2
            for (int t = 0; t < half; t++) {
                const float wa = wp[2 * t], wb = wp[2 * t + 1];
                float2 v;
                v = p0[t]; m0 = fmaxf(m0, v.x + wa); m0 = fmaxf(m0, v.y + wb);
                v = p1[t]; m1 = fmaxf(m1, v.x + wa); m1 = fmaxf(m1, v.y + wb);
                v = p2[t]; m2 = fmaxf(m2, v.x + wa); m2 = fmaxf(m2, v.y + wb);
                v = p3[t]; m3 = fmaxf(m3, v.x + wa); m3 = fmaxf(m3, v.y + wb);
            }
            if (w0) o0[j] = m0;
            if (w1) o1[j] = m1;
            if (w2) o2[j] = m2;
            if (w3) o3[j] = m3;
        };

        #pragma unroll
        for (int s = 0; s < FSLOTS; s++) {
            if (kind[s] == 3) continue;
            const int j = tid + s * THREADS;
            if (kind[s] == 2) { tri4(ia[s], ib[s], (j - jbase) * WSTRIDE, j); continue; }
            float v0, v1, v2, v3;
            if (kind[s] == 0) {
                const int a = ia[s], b = ib[s];
                const float f = ff[s];
                float a0 = xr0[a], b0 = xr0[b]; v0 = a0 + f * (b0 - a0);
                float a1 = xr1[a], b1 = xr1[b]; v1 = a1 + f * (b1 - a1);
                float a2 = xr2[a], b2 = xr2[b]; v2 = a2 + f * (b2 - a2);
                float a3 = xr3[a], b3 = xr3[b]; v3 = a3 + f * (b3 - a3);
            } else {
                const int i0 = ia[s];
                const float f = ff[s];
                v0 = cubic_eval(xr0, i0, f);
                v1 = cubic_eval(xr1, i0, f);
                v2 = cubic_eval(xr2, i0, f);
                v3 = cubic_eval(xr3, i0, f);
            }
            if (w0) o0[j] = v0;
            if (w1) o1[j] = v1;
            if (w2) o2[j] = v2;
            if (w3) o3[j] = v3;
        }

        if (q3 >= 0) tri4(lo3, lp3, wo3, j3);

        __syncthreads();
    }
}

// ---------------------------------------------------------------------------
extern "C" void kernel_launch(void* const* d_in, const int* in_sizes, int n_in_arr,
                              void* d_out, int out_size)
{
    const float* x    = (const float*)d_in[0];
    const float* flin = (const float*)d_in[1];
    const float* fcub = (const float*)d_in[2];
    const float* w    = (const float*)d_in[3];
    const int*   pidx = (const int*)d_in[4];

    const int n_lin = in_sizes[1];
    const int n_cub = in_sizes[2];

    // Solve (n_tri, n_in, n_rows) from the size system; unique factorization.
    int n_tri = 0, N_IN = 0, n_rows = 0;
    for (int t = 1; t <= MAX_TRI; t++) {
        if (in_sizes[3] % t) continue;
        long ni = in_sizes[3] / t;
        if (ni <= 0 || (long)in_sizes[0] % ni) continue;
        long rows = (long)in_sizes[0] / ni;
        if (rows * (long)(n_lin + n_cub + t) == (long)out_size) {
            n_tri = t; N_IN = (int)ni; n_rows = (int)rows;
            break;
        }
    }
    if (n_tri == 0) return;

    prep_kernel<<<n_tri, 256>>>(w, n_tri, N_IN);

    const int N16    = (N_IN + 6) >> 2;
    const int xpitch = 4 * N16 + 8;                       // staged + pad, mult of 4
    const int bufoff = (n_tri * WSTRIDE + 3) & ~3;
    const int smem_bytes = (bufoff + 8 * xpitch) * (int)sizeof(float);
    cudaFuncSetAttribute(logscale_kernel,
                         cudaFuncAttributeMaxDynamicSharedMemorySize, smem_bytes);

    const int n_items = 4 * ((n_rows + 15) / 16);         // 4 rows per item
    int grid = 148 * 2;                                   // persistent: 2 blocks / SM
    if (grid > n_items) grid = n_items;

    logscale_kernel<<<grid, THREADS, smem_bytes>>>(
        x, flin, fcub, pidx, (float*)d_out,
        n_rows, N_IN, n_lin, n_cub, n_tri, xpitch, n_items);
}

// round 14
// speedup vs baseline: 1.3207x; 1.0320x over previous
#include <cuda_runtime.h>
#include <math.h>

#define MAX_TRI   512
#define WSTRIDE   33        // overflow-region stride (>= lenp+1)
#define THREADS   256
#define FSLOTS    3         // fixed slots cover j < jbase + qrem
#define SW_FLOATS 5888      // smem weight pool (floats); actual use ~5000

__device__ float g_cw[MAX_TRI * WSTRIDE * 2];   // compact pool + overflow region
__device__ int   g_lo[MAX_TRI];                 // even-aligned band start
__device__ int   g_len[MAX_TRI];                // padded band length (mult of 4)
__device__ int   g_off[MAX_TRI];                // offset into pool
__device__ int   g_ctr;

// ---------------------------------------------------------------------------
__device__ __forceinline__ void cp_async16(float4* sptr, const float4* gptr)
{
    unsigned s = (unsigned)__cvta_generic_to_shared(sptr);
    asm volatile("cp.async.cg.shared.global [%0], [%1], 16;\n" :: "r"(s), "l"(gptr));
}
#define CP_COMMIT()  asm volatile("cp.async.commit_group;\n" ::)
#define CP_WAIT1()   asm volatile("cp.async.wait_group 1;\n" ::)
#define CP_WAIT0()   asm volatile("cp.async.wait_group 0;\n" ::)

__global__ void zero_ctr_kernel() { g_ctr = 0; }

// ---------------------------------------------------------------------------
// Preprocess: find finite band, even-align start, pad len to mult of 4,
// append one -inf sentinel, pack into the compact pool via atomic offset.
// ---------------------------------------------------------------------------
__global__ void prep_kernel(const float* __restrict__ w, int n_tri, int n_in)
{
    int j = blockIdx.x;
    if (j >= n_tri) return;
    __shared__ int s_lo, s_hi, s_off;
    if (threadIdx.x == 0) { s_lo = n_in; s_hi = 0; }
    __syncthreads();

    const float* row = w + (size_t)j * n_in;
    int lo = n_in, hi = 0;
    const int n4 = n_in >> 2;
    if ((((size_t)row) & 15) == 0) {
        const float4* row4 = (const float4*)row;
        for (int c4 = threadIdx.x; c4 < n4; c4 += blockDim.x) {
            float4 v = row4[c4];
            int c = c4 << 2;
            if (v.x > -1e30f) { lo = min(lo, c);     hi = max(hi, c);     }
            if (v.y > -1e30f) { lo = min(lo, c + 1); hi = max(hi, c + 1); }
            if (v.z > -1e30f) { lo = min(lo, c + 2); hi = max(hi, c + 2); }
            if (v.w > -1e30f) { lo = min(lo, c + 3); hi = max(hi, c + 3); }
        }
        for (int c = (n4 << 2) + threadIdx.x; c < n_in; c += blockDim.x) {
            float v = row[c];
            if (v > -1e30f) { lo = min(lo, c); hi = max(hi, c); }
        }
    } else {
        for (int c = threadIdx.x; c < n_in; c += blockDim.x) {
            float v = row[c];
            if (v > -1e30f) { lo = min(lo, c); hi = max(hi, c); }
        }
    }
    atomicMin(&s_lo, lo);
    atomicMax(&s_hi, hi);
    __syncthreads();

    const int lof = s_lo, hif = s_hi;
    const int L = lof & ~1;                 // even-aligned start
    int len = hif - L + 1;
    if (len > 32) len = 32;                 // safety clamp (actual max ~30)
    const int lenp = (len + 3) & ~3;        // padded, mult of 4, <= 32

    if (threadIdx.x == 0) {
        int o = atomicAdd(&g_ctr, lenp + 1);            // +1 sentinel
        if (o + lenp + 1 > SW_FLOATS)                   // fail-safe: overflow
            o = SW_FLOATS + j * WSTRIDE;                //   -> global region
        g_off[j] = o; g_lo[j] = L; g_len[j] = lenp;
        s_off = o;
    }
    __syncthreads();
    const int off = s_off;
    for (int k = threadIdx.x; k <= lenp; k += blockDim.x) {
        int bin = L + k;
        g_cw[off + k] =
            (k < len && bin >= lof && bin <= hif) ? row[bin] : -INFINITY;
    }
}

__device__ __forceinline__ float cubic_eval(const float* xs, int i0, float f)
{
    float xm = xs[i0 - 1], c0 = xs[i0], c1 = xs[i0 + 1], c2 = xs[i0 + 2];
    return c0 + 0.5f * f * (c1 - xm +
           f * (2.f * xm - 5.f * c0 + 4.f * c1 - c2 +
           f * (3.f * (c0 - c1) + c2 - xm)));
}

// ---------------------------------------------------------------------------
// Main kernel: persistent; 2 same-shift rows per pass; double-buffered 16B
// cp.async staging; compact smem weights; 4 blocks/SM for latency hiding.
// Tri mapping = R8's proven reversed-consecutive (conflict-free, coalesced).
// ---------------------------------------------------------------------------
__global__ void __launch_bounds__(THREADS, 4)
logscale_kernel(const float* __restrict__ x,
                const float* __restrict__ flin,
                const float* __restrict__ fcub,
                const int*   __restrict__ pidx,
                float*       __restrict__ out,
                int n_rows, int n_in, int n_lin, int n_cub, int n_tri,
                int xpitch, int n_items)
{
    extern __shared__ float smem[];
    const int n_out = n_lin + n_cub + n_tri;
    const int jbase = n_lin + n_cub;
    float* sw   = smem;                     // SW_FLOATS compact weights
    float* bufs = smem + SW_FLOATS;         // 2 buffers x 2 rows x xpitch

    const int tid = threadIdx.x;
    const int N16 = (n_in + 6) >> 2;        // float4 count per staged row

    // ---- one-time block init -------------------------------------------
    {
        int cnt = g_ctr; if (cnt > SW_FLOATS) cnt = SW_FLOATS;
        for (int i = tid; i < cnt; i += THREADS) sw[i] = g_cw[i];
    }
    for (int b = 0; b < 4; b++)             // zero never-staged tails
        for (int i = 4 * N16 + tid; i < xpitch; i += THREADS)
            bufs[b * xpitch + i] = 0.f;

    // Tri assignment (R8 style):
    //   shortest bands q = 0..qrem-1 via slot 2 identity (j = tid + 2*THREADS),
    //   rest via reversed map q3 = n_tri-1-tid (consecutive within warps ->
    //   distinct banks mod 32, coalesced stores).
    const int qrem = (n_tri > 256) ? (n_tri - 256) : 0;
    int q3 = n_tri - 1 - tid;
    int lo3 = 0, lp3 = 0, of3 = 0, j3 = 0;
    const bool has3 = (q3 >= qrem);
    if (has3) {
        lo3 = g_lo[q3]; lp3 = g_len[q3]; of3 = g_off[q3]; j3 = jbase + q3;
    }

    // Fixed slots: 0..1 lin/cubic; slot 2 = lin/cubic tail + shortest tri.
    int   kind[FSLOTS], ia[FSLOTS], ib[FSLOTS], ic[FSLOTS];
    float ff[FSLOTS];
    #pragma unroll
    for (int s = 0; s < FSLOTS; s++) {
        const int j = tid + s * THREADS;
        kind[s] = 3; ia[s] = 0; ib[s] = 0; ic[s] = 0; ff[s] = 0.f;
        if (j < n_lin) {
            kind[s] = 0;
            ia[s] = pidx[j];
            ib[s] = pidx[j + n_lin];
            ff[s] = flin[j];
        } else if (j < jbase) {
            kind[s] = 1;
            float fc = fcub[j - n_lin];
            int i0 = (int)floorf(fc);
            ia[s] = i0;
            ff[s] = fc - (float)i0;
        } else if (j < jbase + qrem) {
            kind[s] = 2;
            const int q = j - jbase;
            ia[s] = g_lo[q]; ib[s] = g_len[q]; ic[s] = g_off[q];
        }
    }
    __syncthreads();

    // ---- pipeline ------------------------------------------------------
    const int stride = gridDim.x;

    auto stage = [&](int m, float* dst) {
        const int g = m >> 2, c = m & 3;
        const int rbase = 8 * g + c;
        int r0 = (rbase < n_rows) ? rbase : c;
        int r1 = (rbase + 4 < n_rows) ? (rbase + 4) : r0;
        const float4* a4 = (const float4*)(x + (size_t)r0 * n_in - c);
        const float4* b4 = (const float4*)(x + (size_t)r1 * n_in - c);
        float4* s0 = (float4*)(dst);
        float4* s1 = (float4*)(dst + xpitch);
        for (int t = tid; t < N16; t += THREADS) {
            cp_async16(&s0[t], &a4[t]);
            cp_async16(&s1[t], &b4[t]);
        }
    };

    int m = blockIdx.x;
    float* cur  = bufs;
    float* nbuf = bufs + 2 * xpitch;
    if (m < n_items) stage(m, cur);
    CP_COMMIT();

    for (; m < n_items; m += stride) {
        const int nxt = m + stride;
        if (nxt < n_items) { stage(nxt, nbuf); CP_COMMIT(); CP_WAIT1(); }
        else               { CP_WAIT0(); }
        __syncthreads();

        const int g = m >> 2, c = m & 3;
        const int rbase = 8 * g + c;
        const float* xr0 = cur + c;
        const float* xr1 = cur + xpitch + c;
        const bool w0 = (rbase     < n_rows);
        const bool w1 = (rbase + 4 < n_rows);
        float* o0 = out + (size_t)rbase * n_out;
        float* o1 = o0 + (size_t)4 * n_out;
        const int pi = c & 1;

        // Banded max-plus for one band, both rows.
        auto tri4 = [&](int off, int lo, int lenp, int j) {
            const float* wsrc = (off < SW_FLOATS) ? (sw + off) : (g_cw + off);
            float m0 = -INFINITY, m1 = -INFINITY;
            if (pi) {
                const float wv = wsrc[0];
                m0 = xr0[lo] + wv; m1 = xr1[lo] + wv;
            }
            const float2* p0 = (const float2*)(xr0 + lo + pi);
            const float2* p1 = (const float2*)(xr1 + lo + pi);
            const float*  wp = wsrc + pi;
            const int half = lenp >> 1;
            #pragma unroll 2
            for (int t = 0; t < half; t++) {
                const float wa = wp[2 * t], wb = wp[2 * t + 1];
                float2 v;
                v = p0[t]; m0 = fmaxf(m0, v.x + wa); m0 = fmaxf(m0, v.y + wb);
                v = p1[t]; m1 = fmaxf(m1, v.x + wa); m1 = fmaxf(m1, v.y + wb);
            }
            if (w0) o0[j] = m0;
            if (w1) o1[j] = m1;
        };

        #pragma unroll
        for (int s = 0; s < FSLOTS; s++) {
            if (kind[s] == 3) continue;
            const int j = tid + s * THREADS;
            if (kind[s] == 2) { tri4(ic[s], ia[s], ib[s], j); continue; }
            float v0, v1;
            if (kind[s] == 0) {
                const int a = ia[s], b = ib[s];
                const float f = ff[s];
                float a0 = xr0[a], b0 = xr0[b]; v0 = a0 + f * (b0 - a0);
                float a1 = xr1[a], b1 = xr1[b]; v1 = a1 + f * (b1 - a1);
            } else {
                const int i0 = ia[s];
                const float f = ff[s];
                v0 = cubic_eval(xr0, i0, f);
                v1 = cubic_eval(xr1, i0, f);
            }
            if (w0) o0[j] = v0;
            if (w1) o1[j] = v1;
        }

        if (has3) tri4(of3, lo3, lp3, j3);

        __syncthreads();
        float* t = cur; cur = nbuf; nbuf = t;
    }
}

// ---------------------------------------------------------------------------
extern "C" void kernel_launch(void* const* d_in, const int* in_sizes, int n_in_arr,
                              void* d_out, int out_size)
{
    const float* x    = (const float*)d_in[0];
    const float* flin = (const float*)d_in[1];
    const float* fcub = (const float*)d_in[2];
    const float* w    = (const float*)d_in[3];
    const int*   pidx = (const int*)d_in[4];

    const int n_lin = in_sizes[1];
    const int n_cub = in_sizes[2];

    // Solve (n_tri, n_in, n_rows) from the size system; unique factorization.
    int n_tri = 0, N_IN = 0, n_rows = 0;
    for (int t = 1; t <= MAX_TRI; t++) {
        if (in_sizes[3] % t) continue;
        long ni = in_sizes[3] / t;
        if (ni <= 0 || (long)in_sizes[0] % ni) continue;
        long rows = (long)in_sizes[0] / ni;
        if (rows * (long)(n_lin + n_cub + t) == (long)out_size) {
            n_tri = t; N_IN = (int)ni; n_rows = (int)rows;
            break;
        }
    }
    if (n_tri == 0) return;

    zero_ctr_kernel<<<1, 1>>>();
    prep_kernel<<<n_tri, 256>>>(w, n_tri, N_IN);

    const int N16    = (N_IN + 6) >> 2;
    const int xpitch = 4 * N16 + 4;                       // staged + pad, mult of 4
    const int smem_bytes = (SW_FLOATS + 4 * xpitch) * (int)sizeof(float);
    cudaFuncSetAttribute(logscale_kernel,
                         cudaFuncAttributeMaxDynamicSharedMemorySize, smem_bytes);

    const int n_items = 4 * ((n_rows + 7) / 8);           // 2 rows per item
    int grid = 148 * 4;                                   // persistent: 4 blocks / SM
    if (grid > n_items) grid = n_items;

    logscale_kernel<<<grid, THREADS, smem_bytes>>>(
        x, flin, fcub, pidx, (float*)d_out,
        n_rows, N_IN, n_lin, n_cub, n_tri, xpitch, n_items);
}